// round 13
// baseline (speedup 1.0000x reference)
#include <cuda_runtime.h>
#include <cuda_fp16.h>
#include <cstdint>

#define BATCH 32
#define NN    512
#define FIN   256
#define FOUT  256
#define EE    2

#define BK    32
#define LDF   40        // fp32 tile stride (floats)
#define LDH   40        // fp16 tile stride (halves)
#define NT    256

// all stages now: A-side 128 rows (fp16 10240 or fp32 20480) + B-side 128 rows
#define ST_A32  (128 * LDF * 4)            // 20480
#define ST_A16  (128 * LDH * 2)            // 10240
#define STAGEB  (ST_A32 + ST_A16)          // 30720 (covers both phase layouts)
#define SMEMB   (3 * STAGEB)               // 92160 -> 2 CTAs/SM (184320 <= 228KB)

// scratch (no allocation allowed)
__device__ __half g_hTh[(size_t)BATCH * EE * FOUT * NN];  // [b][e][o][n]
__device__ __half g_WTh[3 * FIN * FOUT];                  // [z][o][f]
// per-(batch, o-half) gate counters (arrive/depart; net zero -> graph-safe)
__device__ int g_bdone[BATCH][2] = {{0}}, g_bgone[BATCH][2] = {{0}};

// ---------------------------------------------------------------- helpers ---
__device__ __forceinline__ uint32_t smem_u32(const void* p) {
    uint32_t a;
    asm("{ .reg .u64 t; cvta.to.shared.u64 t, %1; cvt.u32.u64 %0, t; }" : "=r"(a) : "l"(p));
    return a;
}
__device__ __forceinline__ uint32_t pack_h2(float lo, float hi) {
    uint32_t r;
    asm("cvt.rn.f16x2.f32 %0, %1, %2;" : "=r"(r) : "f"(hi), "f"(lo));
    return r;
}
__device__ __forceinline__ int ldacq(const int* p) {
    int v;
    asm volatile("ld.global.acquire.gpu.b32 %0, [%1];" : "=r"(v) : "l"(p) : "memory");
    return v;
}
__device__ __forceinline__ void mma16816(float* d, const uint32_t* a, uint32_t b0, uint32_t b1) {
    asm volatile(
        "mma.sync.aligned.m16n8k16.row.col.f32.f16.f16.f32 "
        "{%0,%1,%2,%3}, {%4,%5,%6,%7}, {%8,%9}, {%0,%1,%2,%3};"
        : "+f"(d[0]), "+f"(d[1]), "+f"(d[2]), "+f"(d[3])
        : "r"(a[0]), "r"(a[1]), "r"(a[2]), "r"(a[3]), "r"(b0), "r"(b1));
}
#define CP_COMMIT() asm volatile("cp.async.commit_group;" ::: "memory")
#define CP_WAIT1()  asm volatile("cp.async.wait_group 1;" ::: "memory")
#define CP_WAIT0()  asm volatile("cp.async.wait_group 0;" ::: "memory")

__device__ __forceinline__ void cp16(void* s, const void* g) {
    asm volatile("cp.async.cg.shared.global [%0], [%1], 16;"
                 :: "r"(smem_u32(s)), "l"(g) : "memory");
}

template<int ROWS>
__device__ __forceinline__ void load_f32t(const float* __restrict__ g, int ld, float* s, int tid) {
    #pragma unroll
    for (int i = 0; i < ROWS / 32; i++) {
        int idx = i * NT + tid, r = idx >> 3, c = (idx & 7) * 4;
        cp16(s + r * LDF + c, g + (size_t)r * ld + c);
    }
}
template<int ROWS>
__device__ __forceinline__ void load_f16t(const __half* __restrict__ g, int ld, __half* s, int tid) {
    #pragma unroll
    for (int i = 0; i < ROWS / 64; i++) {
        int idx = i * NT + tid, r = idx >> 2, c = (idx & 3) * 8;
        cp16(s + r * LDH + c, g + (size_t)r * ld + c);
    }
}

// one BK=32 chunk, CTA tile 128x128, warp tile 64x32 (wm 0..1, wo 0..3)
// AH: A fp16 / B fp32 (phase 1).  !AH: A fp32 / B fp16 (phase 2).
template<bool AH>
__device__ __forceinline__ void compute_chunk16(const void* As, const void* Bs,
                                                int wm, int wo, int lane, float* acc) {
    const int g = lane >> 2, t = lane & 3;
    #pragma unroll
    for (int ks = 0; ks < 2; ks++) {
        const int k0 = ks * 16;
        uint32_t af[4][4];
        #pragma unroll
        for (int mf = 0; mf < 4; mf++) {
            int r = wm * 64 + mf * 16 + g;
            if (AH) {
                const __half* A = (const __half*)As;
                af[mf][0] = *(const uint32_t*)(A + r * LDH + k0 + 2 * t);
                af[mf][1] = *(const uint32_t*)(A + (r + 8) * LDH + k0 + 2 * t);
                af[mf][2] = *(const uint32_t*)(A + r * LDH + k0 + 8 + 2 * t);
                af[mf][3] = *(const uint32_t*)(A + (r + 8) * LDH + k0 + 8 + 2 * t);
            } else {
                const float* A = (const float*)As;
                float2 v0 = *(const float2*)(A + r * LDF + k0 + 2 * t);
                float2 v1 = *(const float2*)(A + (r + 8) * LDF + k0 + 2 * t);
                float2 v2 = *(const float2*)(A + r * LDF + k0 + 8 + 2 * t);
                float2 v3 = *(const float2*)(A + (r + 8) * LDF + k0 + 8 + 2 * t);
                af[mf][0] = pack_h2(v0.x, v0.y);
                af[mf][1] = pack_h2(v1.x, v1.y);
                af[mf][2] = pack_h2(v2.x, v2.y);
                af[mf][3] = pack_h2(v3.x, v3.y);
            }
        }
        uint32_t bf[4][2];
        #pragma unroll
        for (int nf = 0; nf < 4; nf++) {
            int n = wo * 32 + nf * 8 + g;
            if (AH) {
                const float* B = (const float*)Bs;
                float2 v0 = *(const float2*)(B + n * LDF + k0 + 2 * t);
                float2 v1 = *(const float2*)(B + n * LDF + k0 + 8 + 2 * t);
                bf[nf][0] = pack_h2(v0.x, v0.y);
                bf[nf][1] = pack_h2(v1.x, v1.y);
            } else {
                const __half* B = (const __half*)Bs;
                bf[nf][0] = *(const uint32_t*)(B + n * LDH + k0 + 2 * t);
                bf[nf][1] = *(const uint32_t*)(B + n * LDH + k0 + 8 + 2 * t);
            }
        }
        #pragma unroll
        for (int mf = 0; mf < 4; mf++)
            #pragma unroll
            for (int nf = 0; nf < 4; nf++)
                mma16816(acc + (mf * 4 + nf) * 4, af[mf], bf[nf][0], bf[nf][1]);
    }
}

__device__ __forceinline__ void zero_acc(float* acc) {
    #pragma unroll
    for (int i = 0; i < 64; i++) acc[i] = 0.f;
}

// ---------------------------------------------------------------------------
// k0: W transposes into g_WTh ([f][o] -> [o][f]) as fp16
// ---------------------------------------------------------------------------
__global__ void k0_transpose(const float* __restrict__ W_adj, const float* __restrict__ W2)
{
    __shared__ float t[32][33];
    int z = blockIdx.z;
    const float* src = (z < 2) ? (W_adj + (size_t)z * FIN * FOUT) : W2;
    int bo = blockIdx.x * 32, bf = blockIdx.y * 32;
    int tx = threadIdx.x, ty = threadIdx.y;
    #pragma unroll
    for (int j = 0; j < 32; j += 8) t[ty + j][tx] = src[(size_t)(bf + ty + j) * FOUT + bo + tx];
    __syncthreads();
    __half* dst = g_WTh + (size_t)z * FIN * FOUT;
    #pragma unroll
    for (int j = 0; j < 32; j += 8)
        dst[(size_t)(bo + ty + j) * FIN + bf + tx] = __float2half_rn(t[tx][ty + j]);
}

// ---------------------------------------------------------------------------
// fused k12, CTA tile 128x128, 2 CTAs/SM.
// blockIdx.x in 0..7: oh = x&1 (o half), q = x>>1 (n quarter / m quarter)
// phase 1: hT[o half oh][n quarter q];  gate (b, oh);  phase 2: out[m quarter q][o half oh]
// ---------------------------------------------------------------------------
__global__ __launch_bounds__(NT, 2) void k12_fused(
    const float* __restrict__ X, const float* __restrict__ adj,
    const float* __restrict__ b_adj, const float* __restrict__ b2,
    float* __restrict__ out)
{
    extern __shared__ char smc[];
    const int tid = threadIdx.x, lane = tid & 31, wid = tid >> 5;
    const int wm = wid & 1, wo = wid >> 1;
    const int b = blockIdx.y;
    const int oh = blockIdx.x & 1, q = blockIdx.x >> 1;
    const int g = lane >> 2, t = lane & 3;

    // ------------------- phase 1: hTh[b,e,o,n] = W^T X + bias -------------------
    {
        const int o0 = oh * 128, n0 = q * 128;
        const float* Bm = X + ((size_t)b * NN + n0) * FIN;
        float acc[64];
        zero_acc(acc);

        const int C = 16;
        #define P1_A(c) (g_WTh + (size_t)((c) >> 3) * FIN * FOUT + (size_t)o0 * FIN + ((c) & 7) * BK)
        #define P1_B(c) (Bm + ((c) & 7) * BK)
        #define P1_LD(c, s) do {                                                      \
            char* sb = smc + (s) * STAGEB;                                            \
            load_f16t<128>(P1_A(c), FIN, (__half*)sb, tid);                           \
            load_f32t<128>(P1_B(c), FIN, (float*)(sb + ST_A16), tid);                 \
            CP_COMMIT(); } while (0)

        P1_LD(0, 0);
        P1_LD(1, 1);

        for (int c = 0; c < C; c++) {
            CP_WAIT1();
            __syncthreads();
            if (c + 2 < C) P1_LD(c + 2, (c + 2) % 3); else CP_COMMIT();
            char* sb = smc + (c % 3) * STAGEB;
            compute_chunk16<true>(sb, sb + ST_A16, wm, wo, lane, acc);

            if ((c & 7) == 7) {
                int e = c >> 3;
                #pragma unroll
                for (int mf = 0; mf < 4; mf++) {
                    int r0 = o0 + wm * 64 + mf * 16 + g;
                    float bias0 = b_adj[e * FOUT + r0];
                    float bias1 = b_adj[e * FOUT + r0 + 8];
                    #pragma unroll
                    for (int nf = 0; nf < 4; nf++) {
                        int cc = n0 + wo * 32 + nf * 8 + 2 * t;
                        float* a4 = acc + (mf * 4 + nf) * 4;
                        __half2* d0 = (__half2*)(g_hTh + (((size_t)(b * EE + e) * FOUT) + r0) * NN + cc);
                        __half2* d1 = (__half2*)(g_hTh + (((size_t)(b * EE + e) * FOUT) + r0 + 8) * NN + cc);
                        *d0 = __floats2half2_rn(a4[0] + bias0, a4[1] + bias0);
                        *d1 = __floats2half2_rn(a4[2] + bias1, a4[3] + bias1);
                    }
                }
                zero_acc(acc);
            }
        }
        CP_WAIT0();
        __syncthreads();
        // arrive only (wait deferred past lin2)
        if (tid == 0) {
            __threadfence();
            atomicAdd(&g_bdone[b][oh], 1);
        }
    }

    // ------------------- phase 2: out = relu(lin2 + sum_e adj.hT + b2) ----------
    {
        const int m0 = q * 128, o0 = oh * 128;
        const float*  adjb = adj + (size_t)b * EE * NN * NN + (size_t)m0 * NN;
        const __half* hTb  = g_hTh + (size_t)b * EE * FOUT * NN + (size_t)o0 * NN;
        const float*  Xb   = X + ((size_t)b * NN + m0) * FIN;
        const __half* W2T  = g_WTh + (size_t)2 * FIN * FOUT + (size_t)o0 * FIN;

        float acc[64];
        zero_acc(acc);

        // ---- 2a: lin2 chunks (independent of phase-1 output) ----
        #define PL_LD(c, s) do {                                                      \
            char* sb = smc + (s) * STAGEB;                                            \
            load_f32t<128>(Xb + (c) * BK, FIN, (float*)sb, tid);                      \
            load_f16t<128>(W2T + (c) * BK, FIN, (__half*)(sb + ST_A32), tid);         \
            CP_COMMIT(); } while (0)

        PL_LD(0, 0);
        PL_LD(1, 1);
        for (int c = 0; c < 8; c++) {
            CP_WAIT1();
            __syncthreads();
            if (c + 2 < 8) PL_LD(c + 2, (c + 2) % 3); else CP_COMMIT();
            char* sb = smc + (c % 3) * STAGEB;
            compute_chunk16<false>(sb, sb + ST_A32, wm, wo, lane, acc);
        }
        CP_WAIT0();
        __syncthreads();

        // ---- gate: wait for this (batch, o-half)'s 4 producers ----
        if (tid == 0) {
            while (ldacq(&g_bdone[b][oh]) < 4) __nanosleep(64);
            int g2 = atomicAdd(&g_bgone[b][oh], 1);
            if (g2 == 3) { g_bdone[b][oh] = 0; __threadfence(); g_bgone[b][oh] = 0; }
        }
        __syncthreads();

        // ---- 2b: adjacency chunks ----
        #define PA_LD(c, s) do {                                                      \
            int e_ = (c) >> 4, kc_ = (c) & 15;                                        \
            char* sb = smc + (s) * STAGEB;                                            \
            load_f32t<128>(adjb + (size_t)e_ * NN * NN + kc_ * BK, NN, (float*)sb, tid); \
            load_f16t<128>(hTb + (size_t)e_ * FOUT * NN + kc_ * BK, NN,               \
                           (__half*)(sb + ST_A32), tid);                              \
            CP_COMMIT(); } while (0)

        PA_LD(0, 0);
        PA_LD(1, 1);
        for (int c = 0; c < 32; c++) {
            CP_WAIT1();
            __syncthreads();
            if (c + 2 < 32) PA_LD(c + 2, (c + 2) % 3); else CP_COMMIT();
            char* sb = smc + (c % 3) * STAGEB;
            compute_chunk16<false>(sb, sb + ST_A32, wm, wo, lane, acc);
        }

        // epilogue: + b2[o], relu, store fp32
        #pragma unroll
        for (int mf = 0; mf < 4; mf++) {
            int r0 = m0 + wm * 64 + mf * 16 + g;
            #pragma unroll
            for (int nf = 0; nf < 4; nf++) {
                int cc = o0 + wo * 32 + nf * 8 + 2 * t;
                float bx = b2[cc], by = b2[cc + 1];
                float* a4 = acc + (mf * 4 + nf) * 4;
                float* d0 = out + ((size_t)b * NN + r0) * FOUT + cc;
                float* d1 = out + ((size_t)b * NN + r0 + 8) * FOUT + cc;
                *(float2*)d0 = make_float2(fmaxf(a4[0] + bx, 0.f), fmaxf(a4[1] + by, 0.f));
                *(float2*)d1 = make_float2(fmaxf(a4[2] + bx, 0.f), fmaxf(a4[3] + by, 0.f));
            }
        }
        CP_WAIT0();
    }
}

// ---------------------------------------------------------------------------
extern "C" void kernel_launch(void* const* d_in, const int* in_sizes, int n_in,
                              void* d_out, int out_size)
{
    const float* n_tensor   = (const float*)d_in[0];  // [32,512,256]
    const float* adj_tensor = (const float*)d_in[1];  // [32,2,512,512]
    const float* W_adj      = (const float*)d_in[2];  // [2,256,256]
    const float* b_adj      = (const float*)d_in[3];  // [2,256]
    const float* W2         = (const float*)d_in[4];  // [256,256]
    const float* b2         = (const float*)d_in[5];  // [256]
    float*       out        = (float*)d_out;          // [32,512,256]

    cudaFuncSetAttribute(k12_fused, cudaFuncAttributeMaxDynamicSharedMemorySize, SMEMB);

    k0_transpose<<<dim3(8, 8, 3), dim3(32, 8)>>>(W_adj, W2);
    k12_fused<<<dim3(8, BATCH), NT, SMEMB>>>(n_tensor, adj_tensor, b_adj, b2, out);
}

// round 14
// speedup vs baseline: 1.0760x; 1.0760x over previous
#include <cuda_runtime.h>
#include <cuda_fp16.h>
#include <cstdint>

#define BATCH 32
#define NN    512
#define FIN   256
#define FOUT  256
#define EE    2

#define BK    32
#define LDF   40        // fp32 tile stride (floats)
#define LDH   40        // fp16 tile stride (halves)
#define NT    256

#define K1_ABYTES (128 * LDH * 2)                 // 10240
#define K1_STAGEB (K1_ABYTES + 256 * LDF * 4)     // 51200
#define K2_ABYTES (128 * LDF * 4)                 // 20480
#define K2_STAGEB (K2_ABYTES + 256 * LDH * 2)     // 40960
#define SMEMB     (3 * K1_STAGEB)                 // 153600 (>= 3*K2_STAGEB)

// scratch (no allocation allowed)
__device__ __half g_hTh[(size_t)BATCH * EE * FOUT * NN];  // [b][e][o][n]
__device__ __half g_WTh[3 * FIN * FOUT];                  // [z][o][f]
// per-batch gate counters (arrive/depart; net zero per launch -> graph-safe)
__device__ int g_bdone[BATCH] = {0}, g_bgone[BATCH] = {0};

// ---------------------------------------------------------------- helpers ---
__device__ __forceinline__ uint32_t smem_u32(const void* p) {
    uint32_t a;
    asm("{ .reg .u64 t; cvta.to.shared.u64 t, %1; cvt.u32.u64 %0, t; }" : "=r"(a) : "l"(p));
    return a;
}
__device__ __forceinline__ uint32_t pack_h2(float lo, float hi) {
    uint32_t r;
    asm("cvt.rn.f16x2.f32 %0, %1, %2;" : "=r"(r) : "f"(hi), "f"(lo));
    return r;
}
__device__ __forceinline__ int ldacq(const int* p) {
    int v;
    asm volatile("ld.global.acquire.gpu.b32 %0, [%1];" : "=r"(v) : "l"(p) : "memory");
    return v;
}
__device__ __forceinline__ void mma16816(float* d, const uint32_t* a, uint32_t b0, uint32_t b1) {
    asm volatile(
        "mma.sync.aligned.m16n8k16.row.col.f32.f16.f16.f32 "
        "{%0,%1,%2,%3}, {%4,%5,%6,%7}, {%8,%9}, {%0,%1,%2,%3};"
        : "+f"(d[0]), "+f"(d[1]), "+f"(d[2]), "+f"(d[3])
        : "r"(a[0]), "r"(a[1]), "r"(a[2]), "r"(a[3]), "r"(b0), "r"(b1));
}
#define CP_COMMIT() asm volatile("cp.async.commit_group;" ::: "memory")
#define CP_WAIT1()  asm volatile("cp.async.wait_group 1;" ::: "memory")
#define CP_WAIT0()  asm volatile("cp.async.wait_group 0;" ::: "memory")

__device__ __forceinline__ void cp16(void* s, const void* g) {
    asm volatile("cp.async.cg.shared.global [%0], [%1], 16;"
                 :: "r"(smem_u32(s)), "l"(g) : "memory");
}

template<int ROWS>
__device__ __forceinline__ void load_f32t(const float* __restrict__ g, int ld, float* s, int tid) {
    #pragma unroll
    for (int i = 0; i < ROWS / 32; i++) {
        int idx = i * NT + tid, r = idx >> 3, c = (idx & 7) * 4;
        cp16(s + r * LDF + c, g + (size_t)r * ld + c);
    }
}
template<int ROWS>
__device__ __forceinline__ void load_f16t(const __half* __restrict__ g, int ld, __half* s, int tid) {
    #pragma unroll
    for (int i = 0; i < ROWS / 64; i++) {
        int idx = i * NT + tid, r = idx >> 2, c = (idx & 3) * 8;
        cp16(s + r * LDH + c, g + (size_t)r * ld + c);
    }
}

// one BK=32 chunk, CTA tile 128x256, warp tile 64x64 (wm 0..1, wo 0..3)
// AH: A fp16 / B fp32 (phase 1).  !AH: A fp32 / B fp16 (phase 2).
template<bool AH>
__device__ __forceinline__ void compute_chunk16(const void* As, const void* Bs,
                                                int wm, int wo, int lane, float* acc) {
    const int g = lane >> 2, t = lane & 3;
    #pragma unroll
    for (int ks = 0; ks < 2; ks++) {
        const int k0 = ks * 16;
        uint32_t af[4][4];
        #pragma unroll
        for (int mf = 0; mf < 4; mf++) {
            int r = wm * 64 + mf * 16 + g;
            if (AH) {
                const __half* A = (const __half*)As;
                af[mf][0] = *(const uint32_t*)(A + r * LDH + k0 + 2 * t);
                af[mf][1] = *(const uint32_t*)(A + (r + 8) * LDH + k0 + 2 * t);
                af[mf][2] = *(const uint32_t*)(A + r * LDH + k0 + 8 + 2 * t);
                af[mf][3] = *(const uint32_t*)(A + (r + 8) * LDH + k0 + 8 + 2 * t);
            } else {
                const float* A = (const float*)As;
                float2 v0 = *(const float2*)(A + r * LDF + k0 + 2 * t);
                float2 v1 = *(const float2*)(A + (r + 8) * LDF + k0 + 2 * t);
                float2 v2 = *(const float2*)(A + r * LDF + k0 + 8 + 2 * t);
                float2 v3 = *(const float2*)(A + (r + 8) * LDF + k0 + 8 + 2 * t);
                af[mf][0] = pack_h2(v0.x, v0.y);
                af[mf][1] = pack_h2(v1.x, v1.y);
                af[mf][2] = pack_h2(v2.x, v2.y);
                af[mf][3] = pack_h2(v3.x, v3.y);
            }
        }
        uint32_t bf[8][2];
        #pragma unroll
        for (int nf = 0; nf < 8; nf++) {
            int n = wo * 64 + nf * 8 + g;
            if (AH) {
                const float* B = (const float*)Bs;
                float2 v0 = *(const float2*)(B + n * LDF + k0 + 2 * t);
                float2 v1 = *(const float2*)(B + n * LDF + k0 + 8 + 2 * t);
                bf[nf][0] = pack_h2(v0.x, v0.y);
                bf[nf][1] = pack_h2(v1.x, v1.y);
            } else {
                const __half* B = (const __half*)Bs;
                bf[nf][0] = *(const uint32_t*)(B + n * LDH + k0 + 2 * t);
                bf[nf][1] = *(const uint32_t*)(B + n * LDH + k0 + 8 + 2 * t);
            }
        }
        #pragma unroll
        for (int mf = 0; mf < 4; mf++)
            #pragma unroll
            for (int nf = 0; nf < 8; nf++)
                mma16816(acc + (mf * 8 + nf) * 4, af[mf], bf[nf][0], bf[nf][1]);
    }
}

__device__ __forceinline__ void zero_acc(float* acc) {
    #pragma unroll
    for (int i = 0; i < 128; i++) acc[i] = 0.f;
}

// ---------------------------------------------------------------------------
// k0: W transposes into g_WTh ([f][o] -> [o][f]) as fp16
// ---------------------------------------------------------------------------
__global__ void k0_transpose(const float* __restrict__ W_adj, const float* __restrict__ W2)
{
    __shared__ float t[32][33];
    int z = blockIdx.z;
    const float* src = (z < 2) ? (W_adj + (size_t)z * FIN * FOUT) : W2;
    int bo = blockIdx.x * 32, bf = blockIdx.y * 32;
    int tx = threadIdx.x, ty = threadIdx.y;
    #pragma unroll
    for (int j = 0; j < 32; j += 8) t[ty + j][tx] = src[(size_t)(bf + ty + j) * FOUT + bo + tx];
    __syncthreads();
    __half* dst = g_WTh + (size_t)z * FIN * FOUT;
    #pragma unroll
    for (int j = 0; j < 32; j += 8)
        dst[(size_t)(bo + ty + j) * FIN + bf + tx] = __float2half_rn(t[tx][ty + j]);
}

// ---------------------------------------------------------------------------
// fused k12: phase 1 (hTh gemm) -> arrive; phase 2a (lin2) hides the gate wait;
// phase 2b (adjacency) + fused epilogue.  All loops use wait->barrier->issue order.
// ---------------------------------------------------------------------------
__global__ __launch_bounds__(NT) void k12_fused(
    const float* __restrict__ X, const float* __restrict__ adj,
    const float* __restrict__ b_adj, const float* __restrict__ b2,
    float* __restrict__ out)
{
    extern __shared__ char smc[];
    const int tid = threadIdx.x, lane = tid & 31, wid = tid >> 5;
    const int wm = wid & 1, wo = wid >> 1;
    const int b = blockIdx.y;
    const int g = lane >> 2, t = lane & 3;

    // ------------------- phase 1: hTh[b,e,o,n] = W^T X + bias -------------------
    {
        const int o0 = (blockIdx.x & 1) * 128, n0 = (blockIdx.x >> 1) * 256;
        const float* Bm = X + ((size_t)b * NN + n0) * FIN;
        float acc[128];
        zero_acc(acc);

        const int C = 16;
        #define P1_A(c) (g_WTh + (size_t)((c) >> 3) * FIN * FOUT + (size_t)o0 * FIN + ((c) & 7) * BK)
        #define P1_B(c) (Bm + ((c) & 7) * BK)
        #define P1_LD(c, s) do {                                                      \
            char* sb = smc + (s) * K1_STAGEB;                                         \
            load_f16t<128>(P1_A(c), FIN, (__half*)sb, tid);                           \
            load_f32t<256>(P1_B(c), FIN, (float*)(sb + K1_ABYTES), tid);              \
            CP_COMMIT(); } while (0)

        P1_LD(0, 0);
        P1_LD(1, 1);

        for (int c = 0; c < C; c++) {
            CP_WAIT1();
            __syncthreads();
            if (c + 2 < C) P1_LD(c + 2, (c + 2) % 3); else CP_COMMIT();
            char* sb = smc + (c % 3) * K1_STAGEB;
            compute_chunk16<true>(sb, sb + K1_ABYTES, wm, wo, lane, acc);

            if ((c & 7) == 7) {
                int e = c >> 3;
                #pragma unroll
                for (int mf = 0; mf < 4; mf++) {
                    int r0 = o0 + wm * 64 + mf * 16 + g;
                    float bias0 = b_adj[e * FOUT + r0];
                    float bias1 = b_adj[e * FOUT + r0 + 8];
                    #pragma unroll
                    for (int nf = 0; nf < 8; nf++) {
                        int cc = n0 + wo * 64 + nf * 8 + 2 * t;
                        float* a4 = acc + (mf * 8 + nf) * 4;
                        __half2* d0 = (__half2*)(g_hTh + (((size_t)(b * EE + e) * FOUT) + r0) * NN + cc);
                        __half2* d1 = (__half2*)(g_hTh + (((size_t)(b * EE + e) * FOUT) + r0 + 8) * NN + cc);
                        *d0 = __floats2half2_rn(a4[0] + bias0, a4[1] + bias0);
                        *d1 = __floats2half2_rn(a4[2] + bias1, a4[3] + bias1);
                    }
                }
                zero_acc(acc);
            }
        }
        CP_WAIT0();
        __syncthreads();
        // arrive only (wait deferred past lin2): producer signal for this batch
        if (tid == 0) {
            __threadfence();
            atomicAdd(&g_bdone[b], 1);
        }
    }

    // ------------------- phase 2: out = relu(lin2 + sum_e adj.hT + b2) ----------
    {
        const int m0 = blockIdx.x * 128;
        const float*  adjb = adj + (size_t)b * EE * NN * NN + (size_t)m0 * NN;
        const __half* hTb  = g_hTh + (size_t)b * EE * FOUT * NN;
        const float*  Xb   = X + ((size_t)b * NN + m0) * FIN;
        const __half* W2T  = g_WTh + (size_t)2 * FIN * FOUT;

        float acc[128];
        zero_acc(acc);

        // ---- 2a: lin2 chunks (independent of phase-1 output) ----
        #define PL_LD(c, s) do {                                                      \
            char* sb = smc + (s) * K2_STAGEB;                                         \
            load_f32t<128>(Xb + (c) * BK, FIN, (float*)sb, tid);                      \
            load_f16t<256>(W2T + (c) * BK, FIN, (__half*)(sb + K2_ABYTES), tid);      \
            CP_COMMIT(); } while (0)

        PL_LD(0, 0);
        PL_LD(1, 1);
        for (int c = 0; c < 8; c++) {
            CP_WAIT1();
            __syncthreads();
            if (c + 2 < 8) PL_LD(c + 2, (c + 2) % 3); else CP_COMMIT();
            char* sb = smc + (c % 3) * K2_STAGEB;
            compute_chunk16<false>(sb, sb + K2_ABYTES, wm, wo, lane, acc);
        }
        CP_WAIT0();
        __syncthreads();

        // ---- gate: wait for this batch's 4 hTh producers (mostly done by now) ----
        if (tid == 0) {
            while (ldacq(&g_bdone[b]) < 4) __nanosleep(64);
            int g2 = atomicAdd(&g_bgone[b], 1);
            if (g2 == 3) { g_bdone[b] = 0; __threadfence(); g_bgone[b] = 0; }
        }
        __syncthreads();

        // ---- 2b: adjacency chunks ----
        #define PA_LD(c, s) do {                                                      \
            int e_ = (c) >> 4, kc_ = (c) & 15;                                        \
            char* sb = smc + (s) * K2_STAGEB;                                         \
            load_f32t<128>(adjb + (size_t)e_ * NN * NN + kc_ * BK, NN, (float*)sb, tid); \
            load_f16t<256>(hTb + (size_t)e_ * FOUT * NN + kc_ * BK, NN,               \
                           (__half*)(sb + K2_ABYTES), tid);                           \
            CP_COMMIT(); } while (0)

        PA_LD(0, 0);
        PA_LD(1, 1);
        for (int c = 0; c < 32; c++) {
            CP_WAIT1();
            __syncthreads();
            if (c + 2 < 32) PA_LD(c + 2, (c + 2) % 3); else CP_COMMIT();
            char* sb = smc + (c % 3) * K2_STAGEB;
            compute_chunk16<false>(sb, sb + K2_ABYTES, wm, wo, lane, acc);
        }

        // epilogue: + b2[o], relu, store fp32
        #pragma unroll
        for (int mf = 0; mf < 4; mf++) {
            int r0 = m0 + wm * 64 + mf * 16 + g;
            #pragma unroll
            for (int nf = 0; nf < 8; nf++) {
                int cc = wo * 64 + nf * 8 + 2 * t;
                float bx = b2[cc], by = b2[cc + 1];
                float* a4 = acc + (mf * 8 + nf) * 4;
                float* d0 = out + ((size_t)b * NN + r0) * FOUT + cc;
                float* d1 = out + ((size_t)b * NN + r0 + 8) * FOUT + cc;
                *(float2*)d0 = make_float2(fmaxf(a4[0] + bx, 0.f), fmaxf(a4[1] + by, 0.f));
                *(float2*)d1 = make_float2(fmaxf(a4[2] + bx, 0.f), fmaxf(a4[3] + by, 0.f));
            }
        }
        CP_WAIT0();
    }
}

// ---------------------------------------------------------------------------
extern "C" void kernel_launch(void* const* d_in, const int* in_sizes, int n_in,
                              void* d_out, int out_size)
{
    const float* n_tensor   = (const float*)d_in[0];  // [32,512,256]
    const float* adj_tensor = (const float*)d_in[1];  // [32,2,512,512]
    const float* W_adj      = (const float*)d_in[2];  // [2,256,256]
    const float* b_adj      = (const float*)d_in[3];  // [2,256]
    const float* W2         = (const float*)d_in[4];  // [256,256]
    const float* b2         = (const float*)d_in[5];  // [256]
    float*       out        = (float*)d_out;          // [32,512,256]

    cudaFuncSetAttribute(k12_fused, cudaFuncAttributeMaxDynamicSharedMemorySize, SMEMB);

    k0_transpose<<<dim3(8, 8, 3), dim3(32, 8)>>>(W_adj, W2);
    k12_fused<<<dim3(4, BATCH), NT, SMEMB>>>(n_tensor, adj_tensor, b_adj, b2, out);
}

// round 15
// speedup vs baseline: 1.1651x; 1.0828x over previous
#include <cuda_runtime.h>
#include <cuda_fp16.h>
#include <cstdint>

#define BATCH 32
#define NN    512
#define FIN   256
#define FOUT  256
#define EE    2

#define BK    32
#define BK2   64        // phase-2 K chunk
#define LDF   40        // fp32 stride, BK=32 tiles (floats)
#define LDH   40        // fp16 stride, BK=32 tiles (halves)
#define LDF2  72        // fp32 stride, BK=64 tiles (72 mod 32 == 8 -> conflict-free)
#define LDH2  72        // fp16 stride, BK=64 tiles
#define NT    256

#define K1_ABYTES (128 * LDH * 2)                 // 10240
#define K1_STAGEB (K1_ABYTES + 256 * LDF * 4)     // 51200
#define K2_ABYTES (128 * LDF2 * 4)                // 36864
#define K2_STAGEB (K2_ABYTES + 256 * LDH2 * 2)    // 73728
#define SMEMB     (3 * K2_STAGEB)                 // 221184 (>= 3*K1_STAGEB)

// scratch (no allocation allowed)
__device__ __half g_hTh[(size_t)BATCH * EE * FOUT * NN];  // [b][e][o][n]
__device__ __half g_WTh[3 * FIN * FOUT];                  // [z][o][f]
// per-batch gate counters (arrive/depart; net zero per launch -> graph-safe)
__device__ int g_bdone[BATCH] = {0}, g_bgone[BATCH] = {0};

// ---------------------------------------------------------------- helpers ---
__device__ __forceinline__ uint32_t smem_u32(const void* p) {
    uint32_t a;
    asm("{ .reg .u64 t; cvta.to.shared.u64 t, %1; cvt.u32.u64 %0, t; }" : "=r"(a) : "l"(p));
    return a;
}
__device__ __forceinline__ uint32_t pack_h2(float lo, float hi) {
    uint32_t r;
    asm("cvt.rn.f16x2.f32 %0, %1, %2;" : "=r"(r) : "f"(hi), "f"(lo));
    return r;
}
__device__ __forceinline__ int ldacq(const int* p) {
    int v;
    asm volatile("ld.global.acquire.gpu.b32 %0, [%1];" : "=r"(v) : "l"(p) : "memory");
    return v;
}
__device__ __forceinline__ void mma16816(float* d, const uint32_t* a, uint32_t b0, uint32_t b1) {
    asm volatile(
        "mma.sync.aligned.m16n8k16.row.col.f32.f16.f16.f32 "
        "{%0,%1,%2,%3}, {%4,%5,%6,%7}, {%8,%9}, {%0,%1,%2,%3};"
        : "+f"(d[0]), "+f"(d[1]), "+f"(d[2]), "+f"(d[3])
        : "r"(a[0]), "r"(a[1]), "r"(a[2]), "r"(a[3]), "r"(b0), "r"(b1));
}
#define CP_COMMIT() asm volatile("cp.async.commit_group;" ::: "memory")
#define CP_WAIT1()  asm volatile("cp.async.wait_group 1;" ::: "memory")
#define CP_WAIT0()  asm volatile("cp.async.wait_group 0;" ::: "memory")

__device__ __forceinline__ void cp16(void* s, const void* g) {
    asm volatile("cp.async.cg.shared.global [%0], [%1], 16;"
                 :: "r"(smem_u32(s)), "l"(g) : "memory");
}

// --- BK=32 loaders (phase 1) ---
template<int ROWS>
__device__ __forceinline__ void load_f32t(const float* __restrict__ g, int ld, float* s, int tid) {
    #pragma unroll
    for (int i = 0; i < ROWS / 32; i++) {
        int idx = i * NT + tid, r = idx >> 3, c = (idx & 7) * 4;
        cp16(s + r * LDF + c, g + (size_t)r * ld + c);
    }
}
template<int ROWS>
__device__ __forceinline__ void load_f16t(const __half* __restrict__ g, int ld, __half* s, int tid) {
    #pragma unroll
    for (int i = 0; i < ROWS / 64; i++) {
        int idx = i * NT + tid, r = idx >> 2, c = (idx & 3) * 8;
        cp16(s + r * LDH + c, g + (size_t)r * ld + c);
    }
}
// --- BK=64 loaders (phase 2): 128 rows fp32, 256 rows fp16 ---
__device__ __forceinline__ void load_f32w(const float* __restrict__ g, int ld, float* s, int tid) {
    #pragma unroll
    for (int i = 0; i < 8; i++) {                 // 128 rows x 16 chunks / 256 thr
        int idx = i * NT + tid, r = idx >> 4, c = (idx & 15) * 4;
        cp16(s + r * LDF2 + c, g + (size_t)r * ld + c);
    }
}
__device__ __forceinline__ void load_f16w(const __half* __restrict__ g, int ld, __half* s, int tid) {
    #pragma unroll
    for (int i = 0; i < 8; i++) {                 // 256 rows x 8 chunks / 256 thr
        int idx = i * NT + tid, r = idx >> 3, c = (idx & 7) * 8;
        cp16(s + r * LDH2 + c, g + (size_t)r * ld + c);
    }
}

// --- phase-1 chunk: BK=32, A fp16 (LDH), B fp32 (LDF) ---
__device__ __forceinline__ void chunk_p1(const void* As, const void* Bs,
                                         int wm, int wo, int lane, float* acc) {
    const int g = lane >> 2, t = lane & 3;
    #pragma unroll
    for (int ks = 0; ks < 2; ks++) {
        const int k0 = ks * 16;
        uint32_t af[4][4];
        #pragma unroll
        for (int mf = 0; mf < 4; mf++) {
            int r = wm * 64 + mf * 16 + g;
            const __half* A = (const __half*)As;
            af[mf][0] = *(const uint32_t*)(A + r * LDH + k0 + 2 * t);
            af[mf][1] = *(const uint32_t*)(A + (r + 8) * LDH + k0 + 2 * t);
            af[mf][2] = *(const uint32_t*)(A + r * LDH + k0 + 8 + 2 * t);
            af[mf][3] = *(const uint32_t*)(A + (r + 8) * LDH + k0 + 8 + 2 * t);
        }
        uint32_t bf[8][2];
        #pragma unroll
        for (int nf = 0; nf < 8; nf++) {
            int n = wo * 64 + nf * 8 + g;
            const float* B = (const float*)Bs;
            float2 v0 = *(const float2*)(B + n * LDF + k0 + 2 * t);
            float2 v1 = *(const float2*)(B + n * LDF + k0 + 8 + 2 * t);
            bf[nf][0] = pack_h2(v0.x, v0.y);
            bf[nf][1] = pack_h2(v1.x, v1.y);
        }
        #pragma unroll
        for (int mf = 0; mf < 4; mf++)
            #pragma unroll
            for (int nf = 0; nf < 8; nf++)
                mma16816(acc + (mf * 8 + nf) * 4, af[mf], bf[nf][0], bf[nf][1]);
    }
}

// --- phase-2 chunk: BK=64, A fp32 (LDF2), B fp16 (LDH2) ---
__device__ __forceinline__ void chunk_p2(const void* As, const void* Bs,
                                         int wm, int wo, int lane, float* acc) {
    const int g = lane >> 2, t = lane & 3;
    #pragma unroll
    for (int ks = 0; ks < 4; ks++) {
        const int k0 = ks * 16;
        uint32_t af[4][4];
        #pragma unroll
        for (int mf = 0; mf < 4; mf++) {
            int r = wm * 64 + mf * 16 + g;
            const float* A = (const float*)As;
            float2 v0 = *(const float2*)(A + r * LDF2 + k0 + 2 * t);
            float2 v1 = *(const float2*)(A + (r + 8) * LDF2 + k0 + 2 * t);
            float2 v2 = *(const float2*)(A + r * LDF2 + k0 + 8 + 2 * t);
            float2 v3 = *(const float2*)(A + (r + 8) * LDF2 + k0 + 8 + 2 * t);
            af[mf][0] = pack_h2(v0.x, v0.y);
            af[mf][1] = pack_h2(v1.x, v1.y);
            af[mf][2] = pack_h2(v2.x, v2.y);
            af[mf][3] = pack_h2(v3.x, v3.y);
        }
        uint32_t bf[8][2];
        #pragma unroll
        for (int nf = 0; nf < 8; nf++) {
            int n = wo * 64 + nf * 8 + g;
            const __half* B = (const __half*)Bs;
            bf[nf][0] = *(const uint32_t*)(B + n * LDH2 + k0 + 2 * t);
            bf[nf][1] = *(const uint32_t*)(B + n * LDH2 + k0 + 8 + 2 * t);
        }
        #pragma unroll
        for (int mf = 0; mf < 4; mf++)
            #pragma unroll
            for (int nf = 0; nf < 8; nf++)
                mma16816(acc + (mf * 8 + nf) * 4, af[mf], bf[nf][0], bf[nf][1]);
    }
}

__device__ __forceinline__ void zero_acc(float* acc) {
    #pragma unroll
    for (int i = 0; i < 128; i++) acc[i] = 0.f;
}

// ---------------------------------------------------------------------------
// k0: W transposes into g_WTh ([f][o] -> [o][f]) as fp16
// ---------------------------------------------------------------------------
__global__ void k0_transpose(const float* __restrict__ W_adj, const float* __restrict__ W2)
{
    __shared__ float t[32][33];
    int z = blockIdx.z;
    const float* src = (z < 2) ? (W_adj + (size_t)z * FIN * FOUT) : W2;
    int bo = blockIdx.x * 32, bf = blockIdx.y * 32;
    int tx = threadIdx.x, ty = threadIdx.y;
    #pragma unroll
    for (int j = 0; j < 32; j += 8) t[ty + j][tx] = src[(size_t)(bf + ty + j) * FOUT + bo + tx];
    __syncthreads();
    __half* dst = g_WTh + (size_t)z * FIN * FOUT;
    #pragma unroll
    for (int j = 0; j < 32; j += 8)
        dst[(size_t)(bo + ty + j) * FIN + bf + tx] = __float2half_rn(t[tx][ty + j]);
}

// ---------------------------------------------------------------------------
// fused k12: phase 1 (hTh gemm, BK=32) -> arrive; phase 2a (lin2, BK=64) hides
// the gate wait; phase 2b (adjacency, BK=64) + fused epilogue.
// ---------------------------------------------------------------------------
__global__ __launch_bounds__(NT) void k12_fused(
    const float* __restrict__ X, const float* __restrict__ adj,
    const float* __restrict__ b_adj, const float* __restrict__ b2,
    float* __restrict__ out)
{
    extern __shared__ char smc[];
    const int tid = threadIdx.x, lane = tid & 31, wid = tid >> 5;
    const int wm = wid & 1, wo = wid >> 1;
    const int b = blockIdx.y;
    const int g = lane >> 2, t = lane & 3;

    // ------------------- phase 1: hTh[b,e,o,n] = W^T X + bias -------------------
    {
        const int o0 = (blockIdx.x & 1) * 128, n0 = (blockIdx.x >> 1) * 256;
        const float* Bm = X + ((size_t)b * NN + n0) * FIN;
        float acc[128];
        zero_acc(acc);

        const int C = 16;
        #define P1_A(c) (g_WTh + (size_t)((c) >> 3) * FIN * FOUT + (size_t)o0 * FIN + ((c) & 7) * BK)
        #define P1_B(c) (Bm + ((c) & 7) * BK)
        #define P1_LD(c, s) do {                                                      \
            char* sb = smc + (s) * K1_STAGEB;                                         \
            load_f16t<128>(P1_A(c), FIN, (__half*)sb, tid);                           \
            load_f32t<256>(P1_B(c), FIN, (float*)(sb + K1_ABYTES), tid);              \
            CP_COMMIT(); } while (0)

        P1_LD(0, 0);
        P1_LD(1, 1);

        for (int c = 0; c < C; c++) {
            CP_WAIT1();
            __syncthreads();
            if (c + 2 < C) P1_LD(c + 2, (c + 2) % 3); else CP_COMMIT();
            char* sb = smc + (c % 3) * K1_STAGEB;
            chunk_p1(sb, sb + K1_ABYTES, wm, wo, lane, acc);

            if ((c & 7) == 7) {
                int e = c >> 3;
                #pragma unroll
                for (int mf = 0; mf < 4; mf++) {
                    int r0 = o0 + wm * 64 + mf * 16 + g;
                    float bias0 = b_adj[e * FOUT + r0];
                    float bias1 = b_adj[e * FOUT + r0 + 8];
                    #pragma unroll
                    for (int nf = 0; nf < 8; nf++) {
                        int cc = n0 + wo * 64 + nf * 8 + 2 * t;
                        float* a4 = acc + (mf * 8 + nf) * 4;
                        __half2* d0 = (__half2*)(g_hTh + (((size_t)(b * EE + e) * FOUT) + r0) * NN + cc);
                        __half2* d1 = (__half2*)(g_hTh + (((size_t)(b * EE + e) * FOUT) + r0 + 8) * NN + cc);
                        *d0 = __floats2half2_rn(a4[0] + bias0, a4[1] + bias0);
                        *d1 = __floats2half2_rn(a4[2] + bias1, a4[3] + bias1);
                    }
                }
                zero_acc(acc);
            }
        }
        CP_WAIT0();
        __syncthreads();
        // arrive only (wait deferred past lin2): producer signal for this batch
        if (tid == 0) {
            __threadfence();
            atomicAdd(&g_bdone[b], 1);
        }
    }

    // ------------------- phase 2: out = relu(lin2 + sum_e adj.hT + b2) ----------
    {
        const int m0 = blockIdx.x * 128;
        const float*  adjb = adj + (size_t)b * EE * NN * NN + (size_t)m0 * NN;
        const __half* hTb  = g_hTh + (size_t)b * EE * FOUT * NN;
        const float*  Xb   = X + ((size_t)b * NN + m0) * FIN;
        const __half* W2T  = g_WTh + (size_t)2 * FIN * FOUT;

        float acc[128];
        zero_acc(acc);

        // ---- 2a: lin2, 4 chunks of BK2=64 (independent of phase-1 output) ----
        #define PL_LD(c, s) do {                                                      \
            char* sb = smc + (s) * K2_STAGEB;                                         \
            load_f32w(Xb + (c) * BK2, FIN, (float*)sb, tid);                          \
            load_f16w(W2T + (c) * BK2, FIN, (__half*)(sb + K2_ABYTES), tid);          \
            CP_COMMIT(); } while (0)

        PL_LD(0, 0);
        PL_LD(1, 1);
        for (int c = 0; c < 4; c++) {
            CP_WAIT1();
            __syncthreads();
            if (c + 2 < 4) PL_LD(c + 2, (c + 2) % 3); else CP_COMMIT();
            char* sb = smc + (c % 3) * K2_STAGEB;
            chunk_p2(sb, sb + K2_ABYTES, wm, wo, lane, acc);
        }
        CP_WAIT0();
        __syncthreads();

        // ---- gate: wait for this batch's 4 hTh producers (mostly done by now) ----
        if (tid == 0) {
            while (ldacq(&g_bdone[b]) < 4) __nanosleep(64);
            int g2 = atomicAdd(&g_bgone[b], 1);
            if (g2 == 3) { g_bdone[b] = 0; __threadfence(); g_bgone[b] = 0; }
        }
        __syncthreads();

        // ---- 2b: adjacency, 16 chunks of BK2=64 ----
        #define PA_LD(c, s) do {                                                      \
            int e_ = (c) >> 3, kc_ = (c) & 7;                                         \
            char* sb = smc + (s) * K2_STAGEB;                                         \
            load_f32w(adjb + (size_t)e_ * NN * NN + kc_ * BK2, NN, (float*)sb, tid);  \
            load_f16w(hTb + (size_t)e_ * FOUT * NN + kc_ * BK2, NN,                   \
                      (__half*)(sb + K2_ABYTES), tid);                                \
            CP_COMMIT(); } while (0)

        PA_LD(0, 0);
        PA_LD(1, 1);
        for (int c = 0; c < 16; c++) {
            CP_WAIT1();
            __syncthreads();
            if (c + 2 < 16) PA_LD(c + 2, (c + 2) % 3); else CP_COMMIT();
            char* sb = smc + (c % 3) * K2_STAGEB;
            chunk_p2(sb, sb + K2_ABYTES, wm, wo, lane, acc);
        }

        // epilogue: + b2[o], relu, store fp32
        #pragma unroll
        for (int mf = 0; mf < 4; mf++) {
            int r0 = m0 + wm * 64 + mf * 16 + g;
            #pragma unroll
            for (int nf = 0; nf < 8; nf++) {
                int cc = wo * 64 + nf * 8 + 2 * t;
                float bx = b2[cc], by = b2[cc + 1];
                float* a4 = acc + (mf * 8 + nf) * 4;
                float* d0 = out + ((size_t)b * NN + r0) * FOUT + cc;
                float* d1 = out + ((size_t)b * NN + r0 + 8) * FOUT + cc;
                *(float2*)d0 = make_float2(fmaxf(a4[0] + bx, 0.f), fmaxf(a4[1] + by, 0.f));
                *(float2*)d1 = make_float2(fmaxf(a4[2] + bx, 0.f), fmaxf(a4[3] + by, 0.f));
            }
        }
        CP_WAIT0();
    }
}

// ---------------------------------------------------------------------------
extern "C" void kernel_launch(void* const* d_in, const int* in_sizes, int n_in,
                              void* d_out, int out_size)
{
    const float* n_tensor   = (const float*)d_in[0];  // [32,512,256]
    const float* adj_tensor = (const float*)d_in[1];  // [32,2,512,512]
    const float* W_adj      = (const float*)d_in[2];  // [2,256,256]
    const float* b_adj      = (const float*)d_in[3];  // [2,256]
    const float* W2         = (const float*)d_in[4];  // [256,256]
    const float* b2         = (const float*)d_in[5];  // [256]
    float*       out        = (float*)d_out;          // [32,512,256]

    cudaFuncSetAttribute(k12_fused, cudaFuncAttributeMaxDynamicSharedMemorySize, SMEMB);

    k0_transpose<<<dim3(8, 8, 3), dim3(32, 8)>>>(W_adj, W2);
    k12_fused<<<dim3(4, BATCH), NT, SMEMB>>>(n_tensor, adj_tensor, b_adj, b2, out);
}